// round 1
// baseline (speedup 1.0000x reference)
#include <cuda_runtime.h>
#include <math.h>

#define NN    50000
#define NE    500000
#define FDIM  128
#define VDIM  12
#define TDIM  768
#define RELD  200
#define NETT  3
#define NIDX  10000

// ---------------- scratch (static device globals; no allocation) ----------------
__device__ float g_bufA[NN * FDIM];
__device__ float g_bufB[NN * FDIM];
__device__ float g_Wx[NN * FDIM];
__device__ float g_res[NN * FDIM];
__device__ float g_si[NN];
__device__ float g_sj[NN];
__device__ float g_alpha[NE];
__device__ int   g_deg[NN];
__device__ int   g_cursor[NN];
__device__ int   g_rowptr[NN + 1];
__device__ int   g_srccsr[NE];
__device__ int   g_etcsr[NE];
__device__ int   g_bsum[256];
__device__ int   g_boff[256];
__device__ float g_M1[VDIM * FDIM];
__device__ float g_M2[TDIM * FDIM];
__device__ float g_cvec[FDIM];
__device__ float g_sr[2][NETT];

// ---------------- helpers ----------------
__device__ __forceinline__ float wredsum(float v) {
    #pragma unroll
    for (int o = 16; o; o >>= 1) v += __shfl_xor_sync(0xFFFFFFFFu, v, o);
    return v;
}
__device__ __forceinline__ float wredmax(float v) {
    #pragma unroll
    for (int o = 16; o; o >>= 1) v = fmaxf(v, __shfl_xor_sync(0xFFFFFFFFu, v, o));
    return v;
}

// ---------------- CSR build ----------------
__global__ void k_zero2() {
    int i = blockIdx.x * blockDim.x + threadIdx.x;
    if (i < NN) { g_deg[i] = 0; g_cursor[i] = 0; }
}

__global__ void k_count(const int* __restrict__ dst) {
    int e = blockIdx.x * blockDim.x + threadIdx.x;
    if (e < NE) atomicAdd(&g_deg[dst[e]], 1);
}

__global__ void k_scan1() {
    __shared__ int s[256];
    int t = threadIdx.x;
    int i = blockIdx.x * 256 + t;
    int v = (i < NN) ? g_deg[i] : 0;
    s[t] = v;
    __syncthreads();
    #pragma unroll
    for (int off = 1; off < 256; off <<= 1) {
        int x = (t >= off) ? s[t - off] : 0;
        __syncthreads();
        s[t] += x;
        __syncthreads();
    }
    if (i < NN) g_rowptr[i] = s[t];        // inclusive partial
    if (t == 255) g_bsum[blockIdx.x] = s[255];
}

__global__ void k_scan2(int nb) {
    __shared__ int s[256];
    int t = threadIdx.x;
    int v = (t < nb) ? g_bsum[t] : 0;
    s[t] = v;
    __syncthreads();
    #pragma unroll
    for (int off = 1; off < 256; off <<= 1) {
        int x = (t >= off) ? s[t - off] : 0;
        __syncthreads();
        s[t] += x;
        __syncthreads();
    }
    g_boff[t] = s[t] - v;                  // exclusive block offset
}

__global__ void k_scan3() {
    int i = blockIdx.x * blockDim.x + threadIdx.x;
    if (i < NN) g_rowptr[i] = g_rowptr[i] - g_deg[i] + g_boff[i >> 8];  // exclusive
    if (i == 0) g_rowptr[NN] = NE;
}

__global__ void k_fill(const int* __restrict__ src, const int* __restrict__ dst,
                       const int* __restrict__ et) {
    int e = blockIdx.x * blockDim.x + threadIdx.x;
    if (e < NE) {
        int d = dst[e];
        int slot = g_rowptr[d] + atomicAdd(&g_cursor[d], 1);
        g_srccsr[slot] = src[e];
        g_etcsr[slot]  = et[e];
    }
}

// ---------------- weight precompute (folded front-end + relation scores) ----------------
__global__ void k_prepM1(const float* __restrict__ fc1w, const float* __restrict__ reluw) {
    for (int o = threadIdx.x; o < VDIM * FDIM; o += blockDim.x) {
        int i = o >> 7, j = o & 127;
        float s = 0.f;
        for (int k = 0; k < FDIM; k++) s += fc1w[i * FDIM + k] * reluw[k * FDIM + j];
        g_M1[o] = s;
    }
}

__global__ void k_prepM2(const float* __restrict__ fc2w, const float* __restrict__ reluw) {
    __shared__ float row[FDIM];
    int i = blockIdx.x, j = threadIdx.x;
    row[j] = fc2w[i * FDIM + j];
    __syncthreads();
    float s = 0.f;
    for (int k = 0; k < FDIM; k++) s += row[k] * reluw[(FDIM + k) * FDIM + j];
    g_M2[i * FDIM + j] = s;
}

__global__ void k_prepc(const float* __restrict__ fc1b, const float* __restrict__ fc2b,
                        const float* __restrict__ relub, const float* __restrict__ reluw) {
    int j = threadIdx.x;
    float s = relub[j];
    for (int k = 0; k < FDIM; k++)
        s += fc1b[k] * reluw[k * FDIM + j] + fc2b[k] * reluw[(FDIM + k) * FDIM + j];
    g_cvec[j] = s;
}

__global__ void k_prepsr(const float* __restrict__ rel, const float* __restrict__ Wr,
                         const float* __restrict__ a, int layer) {
    __shared__ float wra[RELD];
    for (int j = threadIdx.x; j < RELD; j += blockDim.x) {
        float s = 0.f;
        for (int k = 0; k < FDIM; k++) s += Wr[j * FDIM + k] * a[2 * FDIM + k];
        wra[j] = s;
    }
    __syncthreads();
    if (threadIdx.x < NETT) {
        float s = 0.f;
        for (int j = 0; j < RELD; j++) s += rel[threadIdx.x * RELD + j] * wra[j];
        g_sr[layer][threadIdx.x] = s;
    }
}

// ---------------- generic SGEMM: C[M,128] = A[M,K] @ B[K,128] (+C)(+bias)(act) ----------------
// act: 0 = none, 1 = leaky_relu(0.01)
__global__ void __launch_bounds__(256) sgemm128(
    const float* __restrict__ A, const float* __restrict__ B, float* __restrict__ C,
    int M, int K, const float* __restrict__ bias, int accum, int act)
{
    __shared__ float As[64][17];     // [m][k], padded
    __shared__ float Bs[16][128];    // [k][n]

    int tid = threadIdx.x;
    int m0  = blockIdx.x * 64;
    int cg  = tid & 31;              // col group: cols cg*4..+3
    int rg  = tid >> 5;              // row group: rows rg*8..+7

    float acc[8][4];
    #pragma unroll
    for (int i = 0; i < 8; i++)
        #pragma unroll
        for (int j = 0; j < 4; j++) acc[i][j] = 0.f;

    for (int k0 = 0; k0 < K; k0 += 16) {
        // A tile: 64 rows x 16 k, float4 along K (all K used are %4==0)
        {
            int m  = tid >> 2;
            int k4 = (tid & 3) * 4;
            int gm = m0 + m, gk = k0 + k4;
            float4 v = make_float4(0.f, 0.f, 0.f, 0.f);
            if (gm < M && gk < K) v = *(const float4*)&A[gm * K + gk];
            As[m][k4 + 0] = v.x; As[m][k4 + 1] = v.y;
            As[m][k4 + 2] = v.z; As[m][k4 + 3] = v.w;
        }
        // B tile: 16 k x 128 n, float4 along N
        #pragma unroll
        for (int i = 0; i < 2; i++) {
            int idx = tid + i * 256;
            int k  = idx >> 5;
            int n4 = (idx & 31) * 4;
            int gk = k0 + k;
            float4 v = make_float4(0.f, 0.f, 0.f, 0.f);
            if (gk < K) v = *(const float4*)&B[gk * 128 + n4];
            *(float4*)&Bs[k][n4] = v;
        }
        __syncthreads();
        #pragma unroll
        for (int k = 0; k < 16; k++) {
            float4 b4 = *(const float4*)&Bs[k][cg * 4];
            float av[8];
            #pragma unroll
            for (int i = 0; i < 8; i++) av[i] = As[rg * 8 + i][k];
            #pragma unroll
            for (int i = 0; i < 8; i++) {
                acc[i][0] += av[i] * b4.x;
                acc[i][1] += av[i] * b4.y;
                acc[i][2] += av[i] * b4.z;
                acc[i][3] += av[i] * b4.w;
            }
        }
        __syncthreads();
    }

    float4 bv = make_float4(0.f, 0.f, 0.f, 0.f);
    if (bias) bv = *(const float4*)&bias[cg * 4];

    #pragma unroll
    for (int i = 0; i < 8; i++) {
        int gm = m0 + rg * 8 + i;
        if (gm < M) {
            float* cp = &C[gm * 128 + cg * 4];
            float4 r;
            r.x = acc[i][0] + bv.x; r.y = acc[i][1] + bv.y;
            r.z = acc[i][2] + bv.z; r.w = acc[i][3] + bv.w;
            if (accum) {
                float4 o = *(const float4*)cp;
                r.x += o.x; r.y += o.y; r.z += o.z; r.w += o.w;
            }
            if (act == 1) {
                r.x = r.x > 0.f ? r.x : 0.01f * r.x;
                r.y = r.y > 0.f ? r.y : 0.01f * r.y;
                r.z = r.z > 0.f ? r.z : 0.01f * r.z;
                r.w = r.w > 0.f ? r.w : 0.01f * r.w;
            }
            *(float4*)cp = r;
        }
    }
}

// ---------------- attention: s_i/s_j, per-node softmax, aggregation ----------------
__global__ void k_sisj(const float* __restrict__ a) {
    int w = (blockIdx.x * blockDim.x + threadIdx.x) >> 5;
    int lane = threadIdx.x & 31;
    if (w >= NN) return;
    float4 x  = *(const float4*)&g_Wx[w * FDIM + lane * 4];
    float4 ai = *(const float4*)&a[lane * 4];
    float4 aj = *(const float4*)&a[FDIM + lane * 4];
    float si = x.x * ai.x + x.y * ai.y + x.z * ai.z + x.w * ai.w;
    float sj = x.x * aj.x + x.y * aj.y + x.z * aj.z + x.w * aj.w;
    si = wredsum(si);
    sj = wredsum(sj);
    if (lane == 0) { g_si[w] = si; g_sj[w] = sj; }
}

__global__ void k_softmax(int layer) {
    int d = (blockIdx.x * blockDim.x + threadIdx.x) >> 5;
    int lane = threadIdx.x & 31;
    if (d >= NN) return;
    int s0 = g_rowptr[d], s1 = g_rowptr[d + 1];
    if (s0 == s1) return;
    const float* srp = g_sr[layer];
    float sid = g_si[d];

    float m = -1e30f;
    for (int i = s0 + lane; i < s1; i += 32) {
        float e = sid + g_sj[g_srccsr[i]] + srp[g_etcsr[i]];
        e = e > 0.f ? e : 0.2f * e;         // leaky_relu(., 0.2)
        g_alpha[i] = e;
        m = fmaxf(m, e);
    }
    m = wredmax(m);

    float s = 0.f;
    for (int i = s0 + lane; i < s1; i += 32) {
        float ex = expf(g_alpha[i] - m);
        g_alpha[i] = ex;
        s += ex;
    }
    s = wredsum(s);
    float rinv = 1.f / s;
    for (int i = s0 + lane; i < s1; i += 32) g_alpha[i] *= rinv;
}

__global__ void k_agg(float* __restrict__ out) {
    int d = (blockIdx.x * blockDim.x + threadIdx.x) >> 5;
    int lane = threadIdx.x & 31;
    if (d >= NN) return;
    int s0 = g_rowptr[d], s1 = g_rowptr[d + 1];
    float4 acc = make_float4(0.f, 0.f, 0.f, 0.f);
    for (int i = s0; i < s1; i++) {          // warp-uniform loop over edges
        float al = g_alpha[i];
        int s = g_srccsr[i];
        float4 w = *(const float4*)&g_Wx[s * FDIM + lane * 4];
        acc.x += al * w.x; acc.y += al * w.y;
        acc.z += al * w.z; acc.w += al * w.w;
    }
    float4 r = *(const float4*)&g_res[d * FDIM + lane * 4];
    acc.x += r.x; acc.y += r.y; acc.z += r.z; acc.w += r.w;
    acc.x = acc.x > 0.f ? acc.x : expm1f(acc.x);   // ELU
    acc.y = acc.y > 0.f ? acc.y : expm1f(acc.y);
    acc.z = acc.z > 0.f ? acc.z : expm1f(acc.z);
    acc.w = acc.w > 0.f ? acc.w : expm1f(acc.w);
    *(float4*)&out[d * FDIM + lane * 4] = acc;
}

// ---------------- output gather + fc3 ----------------
__global__ void k_out(const float* __restrict__ feat, const int* __restrict__ idx,
                      const float* __restrict__ w3, const float* __restrict__ b3,
                      float* __restrict__ out) {
    int i = (blockIdx.x * blockDim.x + threadIdx.x) >> 5;
    int lane = threadIdx.x & 31;
    if (i >= NIDX) return;
    int n = idx[i];
    float4 f = *(const float4*)&feat[n * FDIM + lane * 4];
    float fv[4] = {f.x, f.y, f.z, f.w};
    float s0 = 0.f, s1 = 0.f;
    #pragma unroll
    for (int j = 0; j < 4; j++) {
        int k = lane * 4 + j;
        s0 += fv[j] * w3[k * 2 + 0];
        s1 += fv[j] * w3[k * 2 + 1];
    }
    s0 = wredsum(s0);
    s1 = wredsum(s1);
    if (lane == 0) {
        out[i * 2 + 0] = s0 + b3[0];
        out[i * 2 + 1] = s1 + b3[1];
    }
}

// ---------------- host ----------------
extern "C" void kernel_launch(void* const* d_in, const int* in_sizes, int n_in,
                              void* d_out, int out_size) {
    const float* vf    = (const float*)d_in[0];
    const float* tf    = (const float*)d_in[1];
    const float* fc1w  = (const float*)d_in[2];
    const float* fc1b  = (const float*)d_in[3];
    const float* fc2w  = (const float*)d_in[4];
    const float* fc2b  = (const float*)d_in[5];
    const float* reluw = (const float*)d_in[6];
    const float* relub = (const float*)d_in[7];
    const float* l1W   = (const float*)d_in[8];
    const float* l1Wr  = (const float*)d_in[9];
    const float* l1a   = (const float*)d_in[10];
    const float* l1Wres= (const float*)d_in[11];
    const float* l1rel = (const float*)d_in[12];
    const float* l2W   = (const float*)d_in[13];
    const float* l2Wr  = (const float*)d_in[14];
    const float* l2a   = (const float*)d_in[15];
    const float* l2Wres= (const float*)d_in[16];
    const float* l2rel = (const float*)d_in[17];
    const float* fc3w  = (const float*)d_in[18];
    const float* fc3b  = (const float*)d_in[19];
    const int*   eidx  = (const int*)d_in[20];
    const int*   et    = (const int*)d_in[21];
    const int*   idx   = (const int*)d_in[22];
    float*       out   = (float*)d_out;

    const int* src = eidx;
    const int* dst = eidx + NE;

    void *pA, *pB, *pWx, *pRes, *pM1, *pM2, *pC;
    cudaGetSymbolAddress(&pA,  g_bufA);
    cudaGetSymbolAddress(&pB,  g_bufB);
    cudaGetSymbolAddress(&pWx, g_Wx);
    cudaGetSymbolAddress(&pRes,g_res);
    cudaGetSymbolAddress(&pM1, g_M1);
    cudaGetSymbolAddress(&pM2, g_M2);
    cudaGetSymbolAddress(&pC,  g_cvec);
    float* bufA = (float*)pA;
    float* bufB = (float*)pB;
    float* Wx   = (float*)pWx;
    float* res  = (float*)pRes;
    float* M1   = (float*)pM1;
    float* M2   = (float*)pM2;
    float* cv   = (float*)pC;

    const int NB   = (NN + 255) / 256;          // 196
    const int EB   = (NE + 255) / 256;
    const int gM   = (NN + 63) / 64;            // GEMM M tiles
    const int gW   = (NN * 32 + 255) / 256;     // warp-per-node grids
    const int gOut = (NIDX * 32 + 255) / 256;

    // CSR build (int atomics only)
    k_zero2<<<NB, 256>>>();
    k_count<<<EB, 256>>>(dst);
    k_scan1<<<NB, 256>>>();
    k_scan2<<<1, 256>>>(NB);
    k_scan3<<<NB, 256>>>();
    k_fill<<<EB, 256>>>(src, dst, et);

    // Folded front-end weights + relation scores
    k_prepM1<<<1, 256>>>(fc1w, reluw);
    k_prepM2<<<TDIM, 128>>>(fc2w, reluw);
    k_prepc<<<1, 128>>>(fc1b, fc2b, relub, reluw);
    k_prepsr<<<1, 256>>>(l1rel, l1Wr, l1a, 0);
    k_prepsr<<<1, 256>>>(l2rel, l2Wr, l2a, 1);

    // feat0 = leaky(vf@M1 + tf@M2 + c, 0.01)
    sgemm128<<<gM, 256>>>(vf, M1, bufA, NN, VDIM, nullptr, 0, 0);
    sgemm128<<<gM, 256>>>(tf, M2, bufA, NN, TDIM, cv, 1, 1);

    // layer 1: bufA -> bufB
    sgemm128<<<gM, 256>>>(bufA, l1W,    Wx,  NN, FDIM, nullptr, 0, 0);
    sgemm128<<<gM, 256>>>(bufA, l1Wres, res, NN, FDIM, nullptr, 0, 0);
    k_sisj<<<gW, 256>>>(l1a);
    k_softmax<<<gW, 256>>>(0);
    k_agg<<<gW, 256>>>(bufB);

    // layer 2: bufB -> bufA
    sgemm128<<<gM, 256>>>(bufB, l2W,    Wx,  NN, FDIM, nullptr, 0, 0);
    sgemm128<<<gM, 256>>>(bufB, l2Wres, res, NN, FDIM, nullptr, 0, 0);
    k_sisj<<<gW, 256>>>(l2a);
    k_softmax<<<gW, 256>>>(1);
    k_agg<<<gW, 256>>>(bufA);

    // out = feat[idx] @ fc3_w + fc3_b
    k_out<<<gOut, 256>>>(bufA, idx, fc3w, fc3b, out);
}

// round 3
// speedup vs baseline: 1.5059x; 1.5059x over previous
#include <cuda_runtime.h>
#include <cuda_bf16.h>
#include <math.h>
#include <stdint.h>

#define NN    50000
#define NE    500000
#define FDIM  128
#define VDIM  12
#define TDIM  768
#define RELD  200
#define NETT  3
#define NIDX  10000
#define NTILES 391            // ceil(NN/128)

#define BM 128
#define BN 128
#define BK 64
#define LDSM 72               // BK + 8 pad (row stride 144 B -> conflict-free ldmatrix)

// B image slot offsets (elements) in the split-bf16 weight store
#define SLOT_FRONT  0
#define SLOT_L1W    (128 * TDIM)
#define SLOT_L1WRES (SLOT_L1W + 128 * FDIM)
#define SLOT_L2W    (SLOT_L1WRES + 128 * FDIM)
#define SLOT_L2WRES (SLOT_L2W + 128 * FDIM)
#define BIMG_TOTAL  (SLOT_L2WRES + 128 * FDIM)

// ---------------- scratch (static device globals; no allocation) ----------------
__device__ float g_bufA[NN * FDIM];
__device__ float g_bufB[NN * FDIM];
__device__ float g_Wx[NN * FDIM];
__device__ float g_res[NN * FDIM];
__device__ float g_si[NN];
__device__ float g_sj[NN];
__device__ float g_alpha[NE];
__device__ int   g_deg[NN];
__device__ int   g_cursor[NN];
__device__ int   g_rowptr[NN + 1];
__device__ int   g_srccsr[NE];
__device__ int   g_etcsr[NE];
__device__ int   g_bsum[256];
__device__ int   g_boff[256];
__device__ float g_M1[VDIM * FDIM];
__device__ float g_M2[TDIM * FDIM];
__device__ float g_cvec[FDIM];
__device__ float g_sr[2][NETT];
__device__ __nv_bfloat16 g_BH[BIMG_TOTAL];
__device__ __nv_bfloat16 g_BL[BIMG_TOTAL];

// ---------------- helpers ----------------
__device__ __forceinline__ uint32_t smem_u32(const void* p) {
    uint32_t r;
    asm("{ .reg .u64 t; cvta.to.shared.u64 t, %1; cvt.u32.u64 %0, t; }" : "=r"(r) : "l"(p));
    return r;
}

#define LDM4(r, addr) \
    asm volatile("ldmatrix.sync.aligned.m8n8.x4.shared.b16 {%0,%1,%2,%3}, [%4];" \
        : "=r"((r)[0]), "=r"((r)[1]), "=r"((r)[2]), "=r"((r)[3]) : "r"(addr))

__device__ __forceinline__ void mma16816(float* c, const uint32_t* a, const uint32_t* b) {
    asm volatile("mma.sync.aligned.m16n8k16.row.col.f32.bf16.bf16.f32 "
        "{%0,%1,%2,%3}, {%4,%5,%6,%7}, {%8,%9}, {%0,%1,%2,%3};"
        : "+f"(c[0]), "+f"(c[1]), "+f"(c[2]), "+f"(c[3])
        : "r"(a[0]), "r"(a[1]), "r"(a[2]), "r"(a[3]), "r"(b[0]), "r"(b[1]));
}

__device__ __forceinline__ float wredsum(float v) {
    #pragma unroll
    for (int o = 16; o; o >>= 1) v += __shfl_xor_sync(0xFFFFFFFFu, v, o);
    return v;
}
__device__ __forceinline__ float wredmax(float v) {
    #pragma unroll
    for (int o = 16; o; o >>= 1) v = fmaxf(v, __shfl_xor_sync(0xFFFFFFFFu, v, o));
    return v;
}

__device__ __forceinline__ uint32_t pack2bf(float a, float b) {
    __nv_bfloat16 ha = __float2bfloat16(a), hb = __float2bfloat16(b);
    return (uint32_t)__bfloat16_as_ushort(ha) | ((uint32_t)__bfloat16_as_ushort(hb) << 16);
}

// ---------------- CSR build ----------------
__global__ void k_zero2() {
    int i = blockIdx.x * blockDim.x + threadIdx.x;
    if (i < NN) { g_deg[i] = 0; g_cursor[i] = 0; }
}
__global__ void k_count(const int* __restrict__ dst) {
    int e = blockIdx.x * blockDim.x + threadIdx.x;
    if (e < NE) atomicAdd(&g_deg[dst[e]], 1);
}
__global__ void k_scan1() {
    __shared__ int s[256];
    int t = threadIdx.x, i = blockIdx.x * 256 + t;
    int v = (i < NN) ? g_deg[i] : 0;
    s[t] = v; __syncthreads();
    #pragma unroll
    for (int off = 1; off < 256; off <<= 1) {
        int x = (t >= off) ? s[t - off] : 0;
        __syncthreads(); s[t] += x; __syncthreads();
    }
    if (i < NN) g_rowptr[i] = s[t];
    if (t == 255) g_bsum[blockIdx.x] = s[255];
}
__global__ void k_scan2(int nb) {
    __shared__ int s[256];
    int t = threadIdx.x;
    int v = (t < nb) ? g_bsum[t] : 0;
    s[t] = v; __syncthreads();
    #pragma unroll
    for (int off = 1; off < 256; off <<= 1) {
        int x = (t >= off) ? s[t - off] : 0;
        __syncthreads(); s[t] += x; __syncthreads();
    }
    g_boff[t] = s[t] - v;
}
__global__ void k_scan3() {
    int i = blockIdx.x * blockDim.x + threadIdx.x;
    if (i < NN) g_rowptr[i] = g_rowptr[i] - g_deg[i] + g_boff[i >> 8];
    if (i == 0) g_rowptr[NN] = NE;
}
__global__ void k_fill(const int* __restrict__ src, const int* __restrict__ dst,
                       const int* __restrict__ et) {
    int e = blockIdx.x * blockDim.x + threadIdx.x;
    if (e < NE) {
        int d = dst[e];
        int slot = g_rowptr[d] + atomicAdd(&g_cursor[d], 1);
        g_srccsr[slot] = src[e];
        g_etcsr[slot]  = et[e];
    }
}

// ---------------- weight precompute ----------------
__global__ void k_prepM1(const float* __restrict__ fc1w, const float* __restrict__ reluw) {
    for (int o = threadIdx.x; o < VDIM * FDIM; o += blockDim.x) {
        int i = o >> 7, j = o & 127;
        float s = 0.f;
        for (int k = 0; k < FDIM; k++) s += fc1w[i * FDIM + k] * reluw[k * FDIM + j];
        g_M1[o] = s;
    }
}
__global__ void k_prepM2(const float* __restrict__ fc2w, const float* __restrict__ reluw) {
    __shared__ float row[FDIM];
    int i = blockIdx.x, j = threadIdx.x;
    row[j] = fc2w[i * FDIM + j];
    __syncthreads();
    float s = 0.f;
    for (int k = 0; k < FDIM; k++) s += row[k] * reluw[(FDIM + k) * FDIM + j];
    g_M2[i * FDIM + j] = s;
}
__global__ void k_prepc(const float* __restrict__ fc1b, const float* __restrict__ fc2b,
                        const float* __restrict__ relub, const float* __restrict__ reluw) {
    int j = threadIdx.x;
    float s = relub[j];
    for (int k = 0; k < FDIM; k++)
        s += fc1b[k] * reluw[k * FDIM + j] + fc2b[k] * reluw[(FDIM + k) * FDIM + j];
    g_cvec[j] = s;
}
__global__ void k_prepsr(const float* __restrict__ rel, const float* __restrict__ Wr,
                         const float* __restrict__ a, int layer) {
    __shared__ float wra[RELD];
    for (int j = threadIdx.x; j < RELD; j += blockDim.x) {
        float s = 0.f;
        for (int k = 0; k < FDIM; k++) s += Wr[j * FDIM + k] * a[2 * FDIM + k];
        wra[j] = s;
    }
    __syncthreads();
    if (threadIdx.x < NETT) {
        float s = 0.f;
        for (int j = 0; j < RELD; j++) s += rel[threadIdx.x * RELD + j] * wra[j];
        g_sr[layer][threadIdx.x] = s;
    }
}

// B image: W is [K,128] row-major fp32 -> hi/lo bf16 images stored [n][k]
__global__ void k_prepB(const float* __restrict__ W, int K, int base) {
    int idx = blockIdx.x * blockDim.x + threadIdx.x;
    if (idx >= 128 * K) return;
    int k = idx >> 7, n = idx & 127;
    float v = W[(size_t)k * 128 + n];
    __nv_bfloat16 h = __float2bfloat16(v);
    __nv_bfloat16 l = __float2bfloat16(v - __bfloat162float(h));
    g_BH[base + (size_t)n * K + k] = h;
    g_BL[base + (size_t)n * K + k] = l;
}

// v' = vf @ M1  (K=12, tiny)
__global__ void k_vpart(const float* __restrict__ vf) {
    int r = blockIdx.x, j = threadIdx.x;
    __shared__ float vrow[VDIM];
    if (j < VDIM) vrow[j] = vf[r * VDIM + j];
    __syncthreads();
    float s = 0.f;
    #pragma unroll
    for (int k = 0; k < VDIM; k++) s += vrow[k] * g_M1[k * FDIM + j];
    g_bufB[r * FDIM + j] = s;
}

// ---------------- split-bf16 tensor-core GEMM (mma.sync, sm_100-base safe) ----------------
// out[M,128] = A[M,Ktot] @ W[Ktot,128], 3-pass split: AhBh + AhBl + AlBh
// mode 0: out = D ; mode 1: out = leaky(D + addbuf + bias, 0.01)
#define GEMM_SMEM (4 * BM * LDSM * 2)   // Ah, Al, Bh, Bl tiles = 73728 B

__global__ void __launch_bounds__(256) gemm_bf16(
    const float* __restrict__ A,
    const __nv_bfloat16* __restrict__ BHg, const __nv_bfloat16* __restrict__ BLg,
    float* __restrict__ out, int M, int Ktot,
    const float* __restrict__ addbuf, const float* __restrict__ bias, int mode)
{
    extern __shared__ __nv_bfloat16 sm[];
    const int OFF_AL = BM * LDSM;
    const int OFF_BH = 2 * BM * LDSM;
    const int OFF_BL = 3 * BM * LDSM;

    int tid  = threadIdx.x;
    int lane = tid & 31;
    int wid  = tid >> 5;
    int wm = (wid >> 2) * 64;     // warp row offset (2 warp-rows)
    int wn = (wid & 3) * 32;      // warp col offset (4 warp-cols)
    int m0 = blockIdx.x * BM;

    float acc[4][4][4];
    #pragma unroll
    for (int a = 0; a < 4; a++)
        #pragma unroll
        for (int b = 0; b < 4; b++)
            #pragma unroll
            for (int c = 0; c < 4; c++) acc[a][b][c] = 0.f;

    uint32_t sbase = smem_u32(sm);

    for (int kc = 0; kc < Ktot; kc += BK) {
        __syncthreads();
        // ---- stage A tile (fp32 -> hi/lo bf16), 128 x 64 ----
        #pragma unroll
        for (int i = 0; i < 8; i++) {
            int idx = i * 256 + tid;          // 2048 float4
            int r  = idx >> 4;
            int c4 = (idx & 15) << 2;
            int gr = m0 + r;
            float4 v = make_float4(0.f, 0.f, 0.f, 0.f);
            if (gr < M) v = *(const float4*)(A + (size_t)gr * Ktot + kc + c4);
            __nv_bfloat16 h0 = __float2bfloat16(v.x), h1 = __float2bfloat16(v.y);
            __nv_bfloat16 h2 = __float2bfloat16(v.z), h3 = __float2bfloat16(v.w);
            uint2 hp, lp;
            hp.x = (uint32_t)__bfloat16_as_ushort(h0) | ((uint32_t)__bfloat16_as_ushort(h1) << 16);
            hp.y = (uint32_t)__bfloat16_as_ushort(h2) | ((uint32_t)__bfloat16_as_ushort(h3) << 16);
            lp.x = pack2bf(v.x - __bfloat162float(h0), v.y - __bfloat162float(h1));
            lp.y = pack2bf(v.z - __bfloat162float(h2), v.w - __bfloat162float(h3));
            int so = r * LDSM + c4;
            *(uint2*)&sm[so]          = hp;
            *(uint2*)&sm[OFF_AL + so] = lp;
        }
        // ---- stage B tile (bf16 [n][k] images), 128 x 64 per half ----
        #pragma unroll
        for (int i = 0; i < 4; i++) {
            int idx = i * 256 + tid;          // 1024 uint4 per half
            int n  = idx >> 3;
            int c8 = (idx & 7) << 3;
            size_t go = (size_t)n * Ktot + kc + c8;
            *(uint4*)&sm[OFF_BH + n * LDSM + c8] = *(const uint4*)&BHg[go];
            *(uint4*)&sm[OFF_BL + n * LDSM + c8] = *(const uint4*)&BLg[go];
        }
        __syncthreads();

        // ---- 4 k16 steps of mma ----
        #pragma unroll
        for (int ks = 0; ks < 4; ks++) {
            uint32_t ah[4][4], al[4][4], bh[4][2], bl[4][2];
            int arow = lane & 15;
            int acol = ks * 16 + (lane >> 4) * 8;
            #pragma unroll
            for (int im = 0; im < 4; im++) {
                uint32_t ad = sbase + (uint32_t)(((wm + im * 16 + arow) * LDSM + acol) * 2);
                LDM4(ah[im], ad);
                LDM4(al[im], ad + OFF_AL * 2);
            }
            int brow = (lane >> 4) * 8 + (lane & 7);
            int bcol = ks * 16 + ((lane >> 3) & 1) * 8;
            #pragma unroll
            for (int bp = 0; bp < 2; bp++) {
                uint32_t bd = sbase + (uint32_t)((OFF_BH + (wn + bp * 16 + brow) * LDSM + bcol) * 2);
                uint32_t r[4];
                LDM4(r, bd);
                bh[bp*2][0] = r[0]; bh[bp*2][1] = r[1];
                bh[bp*2+1][0] = r[2]; bh[bp*2+1][1] = r[3];
                LDM4(r, bd + (OFF_BL - OFF_BH) * 2);
                bl[bp*2][0] = r[0]; bl[bp*2][1] = r[1];
                bl[bp*2+1][0] = r[2]; bl[bp*2+1][1] = r[3];
            }
            // pass 1: Ah*Bh
            #pragma unroll
            for (int im = 0; im < 4; im++)
                #pragma unroll
                for (int in = 0; in < 4; in++) mma16816(acc[im][in], ah[im], bh[in]);
            // pass 2: Ah*Bl
            #pragma unroll
            for (int im = 0; im < 4; im++)
                #pragma unroll
                for (int in = 0; in < 4; in++) mma16816(acc[im][in], ah[im], bl[in]);
            // pass 3: Al*Bh
            #pragma unroll
            for (int im = 0; im < 4; im++)
                #pragma unroll
                for (int in = 0; in < 4; in++) mma16816(acc[im][in], al[im], bh[in]);
        }
    }

    // ---- epilogue ----
    int g = lane >> 2, t = lane & 3;
    #pragma unroll
    for (int im = 0; im < 4; im++) {
        #pragma unroll
        for (int in = 0; in < 4; in++) {
            int col = wn + in * 8 + t * 2;
            #pragma unroll
            for (int h = 0; h < 2; h++) {
                int row = m0 + wm + im * 16 + g + h * 8;
                if (row < M) {
                    float v0 = acc[im][in][h * 2 + 0];
                    float v1 = acc[im][in][h * 2 + 1];
                    float* op = out + (size_t)row * FDIM + col;
                    if (mode == 1) {
                        const float* ap = addbuf + (size_t)row * FDIM + col;
                        v0 += ap[0] + bias[col];
                        v1 += ap[1] + bias[col + 1];
                        v0 = v0 > 0.f ? v0 : 0.01f * v0;
                        v1 = v1 > 0.f ? v1 : 0.01f * v1;
                    }
                    float2 wv = make_float2(v0, v1);
                    *(float2*)op = wv;
                }
            }
        }
    }
}

// ---------------- attention ----------------
__global__ void k_sisj(const float* __restrict__ a) {
    int w = (blockIdx.x * blockDim.x + threadIdx.x) >> 5;
    int lane = threadIdx.x & 31;
    if (w >= NN) return;
    float4 x  = *(const float4*)&g_Wx[w * FDIM + lane * 4];
    float4 ai = *(const float4*)&a[lane * 4];
    float4 aj = *(const float4*)&a[FDIM + lane * 4];
    float si = x.x * ai.x + x.y * ai.y + x.z * ai.z + x.w * ai.w;
    float sj = x.x * aj.x + x.y * aj.y + x.z * aj.z + x.w * aj.w;
    si = wredsum(si);
    sj = wredsum(sj);
    if (lane == 0) { g_si[w] = si; g_sj[w] = sj; }
}

__global__ void k_softmax(int layer) {
    int d = (blockIdx.x * blockDim.x + threadIdx.x) >> 5;
    int lane = threadIdx.x & 31;
    if (d >= NN) return;
    int s0 = g_rowptr[d], s1 = g_rowptr[d + 1];
    if (s0 == s1) return;
    const float* srp = g_sr[layer];
    float sid = g_si[d];

    float m = -1e30f;
    for (int i = s0 + lane; i < s1; i += 32) {
        float e = sid + g_sj[g_srccsr[i]] + srp[g_etcsr[i]];
        e = e > 0.f ? e : 0.2f * e;
        g_alpha[i] = e;
        m = fmaxf(m, e);
    }
    m = wredmax(m);

    float s = 0.f;
    for (int i = s0 + lane; i < s1; i += 32) {
        float ex = expf(g_alpha[i] - m);
        g_alpha[i] = ex;
        s += ex;
    }
    s = wredsum(s);
    float rinv = 1.f / s;
    for (int i = s0 + lane; i < s1; i += 32) g_alpha[i] *= rinv;
}

__global__ void k_agg(float* __restrict__ out) {
    int d = (blockIdx.x * blockDim.x + threadIdx.x) >> 5;
    int lane = threadIdx.x & 31;
    if (d >= NN) return;
    int s0 = g_rowptr[d], s1 = g_rowptr[d + 1];
    float4 acc = make_float4(0.f, 0.f, 0.f, 0.f);
    for (int i = s0; i < s1; i++) {
        float al = g_alpha[i];
        int s = g_srccsr[i];
        float4 w = *(const float4*)&g_Wx[s * FDIM + lane * 4];
        acc.x += al * w.x; acc.y += al * w.y;
        acc.z += al * w.z; acc.w += al * w.w;
    }
    float4 r = *(const float4*)&g_res[d * FDIM + lane * 4];
    acc.x += r.x; acc.y += r.y; acc.z += r.z; acc.w += r.w;
    acc.x = acc.x > 0.f ? acc.x : expm1f(acc.x);
    acc.y = acc.y > 0.f ? acc.y : expm1f(acc.y);
    acc.z = acc.z > 0.f ? acc.z : expm1f(acc.z);
    acc.w = acc.w > 0.f ? acc.w : expm1f(acc.w);
    *(float4*)&out[d * FDIM + lane * 4] = acc;
}

__global__ void k_out(const float* __restrict__ feat, const int* __restrict__ idx,
                      const float* __restrict__ w3, const float* __restrict__ b3,
                      float* __restrict__ out) {
    int i = (blockIdx.x * blockDim.x + threadIdx.x) >> 5;
    int lane = threadIdx.x & 31;
    if (i >= NIDX) return;
    int n = idx[i];
    float4 f = *(const float4*)&feat[n * FDIM + lane * 4];
    float fv[4] = {f.x, f.y, f.z, f.w};
    float s0 = 0.f, s1 = 0.f;
    #pragma unroll
    for (int j = 0; j < 4; j++) {
        int k = lane * 4 + j;
        s0 += fv[j] * w3[k * 2 + 0];
        s1 += fv[j] * w3[k * 2 + 1];
    }
    s0 = wredsum(s0);
    s1 = wredsum(s1);
    if (lane == 0) {
        out[i * 2 + 0] = s0 + b3[0];
        out[i * 2 + 1] = s1 + b3[1];
    }
}

// ---------------- host ----------------
extern "C" void kernel_launch(void* const* d_in, const int* in_sizes, int n_in,
                              void* d_out, int out_size) {
    const float* vf    = (const float*)d_in[0];
    const float* tf    = (const float*)d_in[1];
    const float* fc1w  = (const float*)d_in[2];
    const float* fc1b  = (const float*)d_in[3];
    const float* fc2w  = (const float*)d_in[4];
    const float* fc2b  = (const float*)d_in[5];
    const float* reluw = (const float*)d_in[6];
    const float* relub = (const float*)d_in[7];
    const float* l1W   = (const float*)d_in[8];
    const float* l1Wr  = (const float*)d_in[9];
    const float* l1a   = (const float*)d_in[10];
    const float* l1Wres= (const float*)d_in[11];
    const float* l1rel = (const float*)d_in[12];
    const float* l2W   = (const float*)d_in[13];
    const float* l2Wr  = (const float*)d_in[14];
    const float* l2a   = (const float*)d_in[15];
    const float* l2Wres= (const float*)d_in[16];
    const float* l2rel = (const float*)d_in[17];
    const float* fc3w  = (const float*)d_in[18];
    const float* fc3b  = (const float*)d_in[19];
    const int*   eidx  = (const int*)d_in[20];
    const int*   et    = (const int*)d_in[21];
    const int*   idx   = (const int*)d_in[22];
    float*       out   = (float*)d_out;

    const int* src = eidx;
    const int* dst = eidx + NE;

    void *pA, *pB, *pWx, *pRes, *pM2, *pC, *pBH, *pBL;
    cudaGetSymbolAddress(&pA,  g_bufA);
    cudaGetSymbolAddress(&pB,  g_bufB);
    cudaGetSymbolAddress(&pWx, g_Wx);
    cudaGetSymbolAddress(&pRes,g_res);
    cudaGetSymbolAddress(&pM2, g_M2);
    cudaGetSymbolAddress(&pC,  g_cvec);
    cudaGetSymbolAddress(&pBH, g_BH);
    cudaGetSymbolAddress(&pBL, g_BL);
    float* bufA = (float*)pA;
    float* bufB = (float*)pB;
    float* Wx   = (float*)pWx;
    float* res  = (float*)pRes;
    float* M2   = (float*)pM2;
    float* cv   = (float*)pC;
    const __nv_bfloat16* BH = (const __nv_bfloat16*)pBH;
    const __nv_bfloat16* BL = (const __nv_bfloat16*)pBL;

    static int smem_set = 0;
    if (!smem_set) {
        cudaFuncSetAttribute(gemm_bf16, cudaFuncAttributeMaxDynamicSharedMemorySize, GEMM_SMEM);
        smem_set = 1;
    }

    const int NB   = (NN + 255) / 256;
    const int EB   = (NE + 255) / 256;
    const int gW   = (NN * 32 + 255) / 256;
    const int gOut = (NIDX * 32 + 255) / 256;
    const int gPBF = (128 * TDIM + 255) / 256;
    const int gPBL = (128 * FDIM + 255) / 256;

    // CSR build (int atomics only)
    k_zero2<<<NB, 256>>>();
    k_count<<<EB, 256>>>(dst);
    k_scan1<<<NB, 256>>>();
    k_scan2<<<1, 256>>>(NB);
    k_scan3<<<NB, 256>>>();
    k_fill<<<EB, 256>>>(src, dst, et);

    // weight precompute + split-bf16 B images
    k_prepM1<<<1, 256>>>(fc1w, reluw);
    k_prepM2<<<TDIM, 128>>>(fc2w, reluw);
    k_prepc<<<1, 128>>>(fc1b, fc2b, relub, reluw);
    k_prepsr<<<1, 256>>>(l1rel, l1Wr, l1a, 0);
    k_prepsr<<<1, 256>>>(l2rel, l2Wr, l2a, 1);
    k_prepB<<<gPBF, 256>>>(M2,     TDIM, SLOT_FRONT);
    k_prepB<<<gPBL, 256>>>(l1W,    FDIM, SLOT_L1W);
    k_prepB<<<gPBL, 256>>>(l1Wres, FDIM, SLOT_L1WRES);
    k_prepB<<<gPBL, 256>>>(l2W,    FDIM, SLOT_L2W);
    k_prepB<<<gPBL, 256>>>(l2Wres, FDIM, SLOT_L2WRES);

    // front end: feat0 = leaky(tf@M2 + vf@M1 + cvec) -> bufA
    k_vpart<<<NN, 128>>>(vf);
    gemm_bf16<<<NTILES, 256, GEMM_SMEM>>>(tf, BH + SLOT_FRONT, BL + SLOT_FRONT,
                                          bufA, NN, TDIM, bufB, cv, 1);

    // layer 1: bufA -> bufB
    gemm_bf16<<<NTILES, 256, GEMM_SMEM>>>(bufA, BH + SLOT_L1W, BL + SLOT_L1W,
                                          Wx, NN, FDIM, nullptr, nullptr, 0);
    gemm_bf16<<<NTILES, 256, GEMM_SMEM>>>(bufA, BH + SLOT_L1WRES, BL + SLOT_L1WRES,
                                          res, NN, FDIM, nullptr, nullptr, 0);
    k_sisj<<<gW, 256>>>(l1a);
    k_softmax<<<gW, 256>>>(0);
    k_agg<<<gW, 256>>>(bufB);

    // layer 2: bufB -> bufA
    gemm_bf16<<<NTILES, 256, GEMM_SMEM>>>(bufB, BH + SLOT_L2W, BL + SLOT_L2W,
                                          Wx, NN, FDIM, nullptr, nullptr, 0);
    gemm_bf16<<<NTILES, 256, GEMM_SMEM>>>(bufB, BH + SLOT_L2WRES, BL + SLOT_L2WRES,
                                          res, NN, FDIM, nullptr, nullptr, 0);
    k_sisj<<<gW, 256>>>(l2a);
    k_softmax<<<gW, 256>>>(1);
    k_agg<<<gW, 256>>>(bufA);

    // output
    k_out<<<gOut, 256>>>(bufA, idx, fc3w, fc3b, out);
}

// round 4
// speedup vs baseline: 1.5825x; 1.0509x over previous
#include <cuda_runtime.h>
#include <cuda_bf16.h>
#include <math.h>
#include <stdint.h>

#define NN    50000
#define NE    500000
#define FDIM  128
#define VDIM  12
#define TDIM  768
#define RELD  200
#define NETT  3
#define NIDX  10000
#define NTILES 391            // ceil(NN/128)

#define BM 128
#define LDSM 72               // 64 + 8 pad (conflict-free ldmatrix, stride 144 B)
#define F_SUB  (BM * LDSM)    // 9216 elems: one 128x64 subtile
#define F_BUF  (4 * F_SUB)    // Ah|Al|Bh|Bl per buffer
#define L_LDA 136             // layer A stride (128 + 8 pad)
#define L_AH  0
#define L_AL  (BM * L_LDA)            // 17408
#define L_B   (2 * BM * L_LDA)        // 34816 (Bh), Bl at +F_SUB

#define GEMM_FRONT_SMEM (2 * F_BUF * 2 + 3072 * 4)          // 159744 B
#define GEMM_LAYER_SMEM ((2 * BM * L_LDA + 2 * F_SUB) * 2 + 1024)  // 107520 B

// B image slot offsets (elements) in the split-bf16 weight store
#define SLOT_FRONT  0
#define SLOT_L1W    (128 * TDIM)
#define SLOT_L1WRES (SLOT_L1W + 128 * FDIM)
#define SLOT_L2W    (SLOT_L1WRES + 128 * FDIM)
#define SLOT_L2WRES (SLOT_L2W + 128 * FDIM)
#define BIMG_TOTAL  (SLOT_L2WRES + 128 * FDIM)

// ---------------- scratch ----------------
__device__ float g_bufA[NN * FDIM];
__device__ float g_bufB[NN * FDIM];
__device__ float g_Wx[NN * FDIM];
__device__ float g_res[NN * FDIM];
__device__ float g_si[NN];
__device__ float g_sj[NN];
__device__ int   g_deg[NN];
__device__ int   g_cursor[NN];
__device__ int   g_rowptr[NN + 1];
__device__ int   g_srccsr[NE];
__device__ int   g_etcsr[NE];
__device__ int   g_bsum[256];
__device__ int   g_boff[256];
__device__ float g_M1[VDIM * FDIM];
__device__ float g_M2[TDIM * FDIM];
__device__ float g_cvec[FDIM];
__device__ float g_sr[2][NETT];
__device__ __nv_bfloat16 g_BH[BIMG_TOTAL];
__device__ __nv_bfloat16 g_BL[BIMG_TOTAL];

// ---------------- helpers ----------------
__device__ __forceinline__ uint32_t smem_u32(const void* p) {
    uint32_t r;
    asm("{ .reg .u64 t; cvta.to.shared.u64 t, %1; cvt.u32.u64 %0, t; }" : "=r"(r) : "l"(p));
    return r;
}

#define LDM4(r, addr) \
    asm volatile("ldmatrix.sync.aligned.m8n8.x4.shared.b16 {%0,%1,%2,%3}, [%4];" \
        : "=r"((r)[0]), "=r"((r)[1]), "=r"((r)[2]), "=r"((r)[3]) : "r"(addr))

__device__ __forceinline__ void mma16816(float* c, const uint32_t* a, const uint32_t* b) {
    asm volatile("mma.sync.aligned.m16n8k16.row.col.f32.bf16.bf16.f32 "
        "{%0,%1,%2,%3}, {%4,%5,%6,%7}, {%8,%9}, {%0,%1,%2,%3};"
        : "+f"(c[0]), "+f"(c[1]), "+f"(c[2]), "+f"(c[3])
        : "r"(a[0]), "r"(a[1]), "r"(a[2]), "r"(a[3]), "r"(b[0]), "r"(b[1]));
}

__device__ __forceinline__ float wredsum(float v) {
    #pragma unroll
    for (int o = 16; o; o >>= 1) v += __shfl_xor_sync(0xFFFFFFFFu, v, o);
    return v;
}
__device__ __forceinline__ float wredmax(float v) {
    #pragma unroll
    for (int o = 16; o; o >>= 1) v = fmaxf(v, __shfl_xor_sync(0xFFFFFFFFu, v, o));
    return v;
}
__device__ __forceinline__ uint32_t pack2bf(float a, float b) {
    __nv_bfloat16 ha = __float2bfloat16(a), hb = __float2bfloat16(b);
    return (uint32_t)__bfloat16_as_ushort(ha) | ((uint32_t)__bfloat16_as_ushort(hb) << 16);
}

// ---------------- CSR build ----------------
__global__ void k_zero2() {
    int i = blockIdx.x * blockDim.x + threadIdx.x;
    if (i < NN) { g_deg[i] = 0; g_cursor[i] = 0; }
}
__global__ void k_count(const int* __restrict__ dst) {
    int e = blockIdx.x * blockDim.x + threadIdx.x;
    if (e < NE) atomicAdd(&g_deg[dst[e]], 1);
}
__global__ void k_scan1() {
    __shared__ int s[256];
    int t = threadIdx.x, i = blockIdx.x * 256 + t;
    int v = (i < NN) ? g_deg[i] : 0;
    s[t] = v; __syncthreads();
    #pragma unroll
    for (int off = 1; off < 256; off <<= 1) {
        int x = (t >= off) ? s[t - off] : 0;
        __syncthreads(); s[t] += x; __syncthreads();
    }
    if (i < NN) g_rowptr[i] = s[t];
    if (t == 255) g_bsum[blockIdx.x] = s[255];
}
__global__ void k_scan2(int nb) {
    __shared__ int s[256];
    int t = threadIdx.x;
    int v = (t < nb) ? g_bsum[t] : 0;
    s[t] = v; __syncthreads();
    #pragma unroll
    for (int off = 1; off < 256; off <<= 1) {
        int x = (t >= off) ? s[t - off] : 0;
        __syncthreads(); s[t] += x; __syncthreads();
    }
    g_boff[t] = s[t] - v;
}
__global__ void k_scan3() {
    int i = blockIdx.x * blockDim.x + threadIdx.x;
    if (i < NN) g_rowptr[i] = g_rowptr[i] - g_deg[i] + g_boff[i >> 8];
    if (i == 0) g_rowptr[NN] = NE;
}
__global__ void k_fill(const int* __restrict__ src, const int* __restrict__ dst,
                       const int* __restrict__ et) {
    int e = blockIdx.x * blockDim.x + threadIdx.x;
    if (e < NE) {
        int d = dst[e];
        int slot = g_rowptr[d] + atomicAdd(&g_cursor[d], 1);
        g_srccsr[slot] = src[e];
        g_etcsr[slot]  = et[e];
    }
}

// ---------------- weight precompute ----------------
__global__ void k_prepM1(const float* __restrict__ fc1w, const float* __restrict__ reluw) {
    for (int o = threadIdx.x; o < VDIM * FDIM; o += blockDim.x) {
        int i = o >> 7, j = o & 127;
        float s = 0.f;
        for (int k = 0; k < FDIM; k++) s += fc1w[i * FDIM + k] * reluw[k * FDIM + j];
        g_M1[o] = s;
    }
}
__global__ void k_prepM2(const float* __restrict__ fc2w, const float* __restrict__ reluw) {
    __shared__ float row[FDIM];
    int i = blockIdx.x, j = threadIdx.x;
    row[j] = fc2w[i * FDIM + j];
    __syncthreads();
    float s = 0.f;
    for (int k = 0; k < FDIM; k++) s += row[k] * reluw[(FDIM + k) * FDIM + j];
    g_M2[i * FDIM + j] = s;
}
__global__ void k_prepc(const float* __restrict__ fc1b, const float* __restrict__ fc2b,
                        const float* __restrict__ relub, const float* __restrict__ reluw) {
    int j = threadIdx.x;
    float s = relub[j];
    for (int k = 0; k < FDIM; k++)
        s += fc1b[k] * reluw[k * FDIM + j] + fc2b[k] * reluw[(FDIM + k) * FDIM + j];
    g_cvec[j] = s;
}
__global__ void k_prepsr(const float* __restrict__ rel, const float* __restrict__ Wr,
                         const float* __restrict__ a, int layer) {
    __shared__ float wra[RELD];
    for (int j = threadIdx.x; j < RELD; j += blockDim.x) {
        float s = 0.f;
        for (int k = 0; k < FDIM; k++) s += Wr[j * FDIM + k] * a[2 * FDIM + k];
        wra[j] = s;
    }
    __syncthreads();
    if (threadIdx.x < NETT) {
        float s = 0.f;
        for (int j = 0; j < RELD; j++) s += rel[threadIdx.x * RELD + j] * wra[j];
        g_sr[layer][threadIdx.x] = s;
    }
}
// W [K,128] fp32 -> hi/lo bf16 images [n][k]
__global__ void k_prepB(const float* __restrict__ W, int K, int base) {
    int idx = blockIdx.x * blockDim.x + threadIdx.x;
    if (idx >= 128 * K) return;
    int k = idx >> 7, n = idx & 127;
    float v = W[(size_t)k * 128 + n];
    __nv_bfloat16 h = __float2bfloat16(v);
    __nv_bfloat16 l = __float2bfloat16(v - __bfloat162float(h));
    g_BH[base + (size_t)n * K + k] = h;
    g_BL[base + (size_t)n * K + k] = l;
}

// ---------------- shared mma inner block (buffer layout Ah|Al|Bh|Bl, stride LDSM) ----------------
__device__ __forceinline__ void mma_block(uint32_t sbase, int bo, int wm, int wn, int lane,
                                          float acc[4][4][4]) {
    #pragma unroll
    for (int ks = 0; ks < 4; ks++) {
        uint32_t ah[4][4], al[4][4], bh[4][2], bl[4][2];
        int arow = lane & 15;
        int acol = ks * 16 + (lane >> 4) * 8;
        #pragma unroll
        for (int im = 0; im < 4; im++) {
            uint32_t ad = sbase + (uint32_t)((bo + (wm + im * 16 + arow) * LDSM + acol) * 2);
            LDM4(ah[im], ad);
            LDM4(al[im], ad + F_SUB * 2);
        }
        int brow = (lane >> 4) * 8 + (lane & 7);
        int bcol = ks * 16 + ((lane >> 3) & 1) * 8;
        #pragma unroll
        for (int bp = 0; bp < 2; bp++) {
            uint32_t bd = sbase + (uint32_t)((bo + 2 * F_SUB + (wn + bp * 16 + brow) * LDSM + bcol) * 2);
            uint32_t r[4];
            LDM4(r, bd);
            bh[bp*2][0] = r[0]; bh[bp*2][1] = r[1];
            bh[bp*2+1][0] = r[2]; bh[bp*2+1][1] = r[3];
            LDM4(r, bd + F_SUB * 2);
            bl[bp*2][0] = r[0]; bl[bp*2][1] = r[1];
            bl[bp*2+1][0] = r[2]; bl[bp*2+1][1] = r[3];
        }
        #pragma unroll
        for (int im = 0; im < 4; im++)
            #pragma unroll
            for (int in = 0; in < 4; in++) mma16816(acc[im][in], ah[im], bh[in]);
        #pragma unroll
        for (int im = 0; im < 4; im++)
            #pragma unroll
            for (int in = 0; in < 4; in++) mma16816(acc[im][in], ah[im], bl[in]);
        #pragma unroll
        for (int im = 0; im < 4; im++)
            #pragma unroll
            for (int in = 0; in < 4; in++) mma16816(acc[im][in], al[im], bh[in]);
    }
}

// ---------------- front GEMM: leaky(tf@M2 + vf@M1 + cvec), double-buffered ----------------
__global__ void __launch_bounds__(256) gemm_front(
    const float* __restrict__ A, const __nv_bfloat16* __restrict__ BHg,
    const __nv_bfloat16* __restrict__ BLg, const float* __restrict__ vf,
    float* __restrict__ out, int M)
{
    extern __shared__ __nv_bfloat16 sm[];
    float* sVf = (float*)(sm + 2 * F_BUF);
    float* sM1 = sVf + 1536;

    int tid = threadIdx.x, lane = tid & 31, wid = tid >> 5;
    int wm = (wid >> 2) * 64, wn = (wid & 3) * 32;
    int m0 = blockIdx.x * BM;

    for (int i = tid; i < 1536; i += 256) {
        int r = i / 12, k = i - r * 12;
        int gr = m0 + r;
        sVf[i] = (gr < M) ? vf[(size_t)gr * VDIM + k] : 0.f;
        sM1[i] = g_M1[i];
    }

    float acc[4][4][4];
    #pragma unroll
    for (int a = 0; a < 4; a++)
        #pragma unroll
        for (int b = 0; b < 4; b++)
            #pragma unroll
            for (int c = 0; c < 4; c++) acc[a][b][c] = 0.f;

    uint32_t sbase = smem_u32(sm);
    float4 areg[8];
    uint4  bhreg[4], blreg[4];

#define F_LOAD(kc) do { \
    _Pragma("unroll") \
    for (int i = 0; i < 8; i++) { \
        int idx = i * 256 + tid; int r = idx >> 4; int c4 = (idx & 15) << 2; int gr = m0 + r; \
        areg[i] = (gr < M) ? *(const float4*)(A + (size_t)gr * TDIM + (kc) + c4) \
                           : make_float4(0.f, 0.f, 0.f, 0.f); } \
    _Pragma("unroll") \
    for (int i = 0; i < 4; i++) { \
        int idx = i * 256 + tid; int n = idx >> 3; int c8 = (idx & 7) << 3; \
        size_t go = (size_t)n * TDIM + (kc) + c8; \
        bhreg[i] = *(const uint4*)&BHg[go]; blreg[i] = *(const uint4*)&BLg[go]; } \
} while (0)

#define F_STORE(bo) do { \
    _Pragma("unroll") \
    for (int i = 0; i < 8; i++) { \
        int idx = i * 256 + tid; int r = idx >> 4; int c4 = (idx & 15) << 2; \
        float4 v = areg[i]; \
        __nv_bfloat16 h0 = __float2bfloat16(v.x), h1 = __float2bfloat16(v.y); \
        __nv_bfloat16 h2 = __float2bfloat16(v.z), h3 = __float2bfloat16(v.w); \
        uint2 hp, lp; \
        hp.x = (uint32_t)__bfloat16_as_ushort(h0) | ((uint32_t)__bfloat16_as_ushort(h1) << 16); \
        hp.y = (uint32_t)__bfloat16_as_ushort(h2) | ((uint32_t)__bfloat16_as_ushort(h3) << 16); \
        lp.x = pack2bf(v.x - __bfloat162float(h0), v.y - __bfloat162float(h1)); \
        lp.y = pack2bf(v.z - __bfloat162float(h2), v.w - __bfloat162float(h3)); \
        int so = (bo) + r * LDSM + c4; \
        *(uint2*)&sm[so] = hp; *(uint2*)&sm[so + F_SUB] = lp; } \
    _Pragma("unroll") \
    for (int i = 0; i < 4; i++) { \
        int idx = i * 256 + tid; int n = idx >> 3; int c8 = (idx & 7) << 3; \
        int so = (bo) + 2 * F_SUB + n * LDSM + c8; \
        *(uint4*)&sm[so] = bhreg[i]; *(uint4*)&sm[so + F_SUB] = blreg[i]; } \
} while (0)

    F_LOAD(0);
    F_STORE(0);
    __syncthreads();

    const int NC = TDIM / 64;   // 12
    for (int c = 0; c < NC; c++) {
        if (c + 1 < NC) F_LOAD((c + 1) * 64);
        mma_block(sbase, (c & 1) * F_BUF, wm, wn, lane, acc);
        if (c + 1 < NC) {
            F_STORE(((c + 1) & 1) * F_BUF);
            __syncthreads();
        }
    }
#undef F_LOAD
#undef F_STORE

    // epilogue: + vf@M1 + cvec, leaky(0.01)
    int g = lane >> 2, t = lane & 3;
    #pragma unroll
    for (int im = 0; im < 4; im++) {
        #pragma unroll
        for (int in = 0; in < 4; in++) {
            int col = wn + in * 8 + t * 2;
            #pragma unroll
            for (int h = 0; h < 2; h++) {
                int rl = wm + im * 16 + g + h * 8;
                int row = m0 + rl;
                if (row < M) {
                    float v0 = acc[im][in][h * 2 + 0] + g_cvec[col];
                    float v1 = acc[im][in][h * 2 + 1] + g_cvec[col + 1];
                    const float* vr = sVf + rl * 12;
                    #pragma unroll
                    for (int k = 0; k < 12; k++) {
                        float vv = vr[k];
                        v0 += vv * sM1[k * 128 + col];
                        v1 += vv * sM1[k * 128 + col + 1];
                    }
                    v0 = v0 > 0.f ? v0 : 0.01f * v0;
                    v1 = v1 > 0.f ? v1 : 0.01f * v1;
                    *(float2*)(out + (size_t)row * FDIM + col) = make_float2(v0, v1);
                }
            }
        }
    }
}

// ---------------- fused layer GEMM: Wx + res + si/sj, A staged once ----------------
__device__ __forceinline__ void mma_layer(uint32_t sbase, int c, int wm, int wn, int lane,
                                          float acc[4][4][4]) {
    #pragma unroll
    for (int ks = 0; ks < 4; ks++) {
        uint32_t ah[4][4], al[4][4], bh[4][2], bl[4][2];
        int arow = lane & 15;
        int acol = c * 64 + ks * 16 + (lane >> 4) * 8;
        #pragma unroll
        for (int im = 0; im < 4; im++) {
            uint32_t ad = sbase + (uint32_t)(((wm + im * 16 + arow) * L_LDA + acol) * 2);
            LDM4(ah[im], ad);
            LDM4(al[im], ad + L_AL * 2);
        }
        int brow = (lane >> 4) * 8 + (lane & 7);
        int bcol = ks * 16 + ((lane >> 3) & 1) * 8;
        #pragma unroll
        for (int bp = 0; bp < 2; bp++) {
            uint32_t bd = sbase + (uint32_t)((L_B + (wn + bp * 16 + brow) * LDSM + bcol) * 2);
            uint32_t r[4];
            LDM4(r, bd);
            bh[bp*2][0] = r[0]; bh[bp*2][1] = r[1];
            bh[bp*2+1][0] = r[2]; bh[bp*2+1][1] = r[3];
            LDM4(r, bd + F_SUB * 2);
            bl[bp*2][0] = r[0]; bl[bp*2][1] = r[1];
            bl[bp*2+1][0] = r[2]; bl[bp*2+1][1] = r[3];
        }
        #pragma unroll
        for (int im = 0; im < 4; im++)
            #pragma unroll
            for (int in = 0; in < 4; in++) mma16816(acc[im][in], ah[im], bh[in]);
        #pragma unroll
        for (int im = 0; im < 4; im++)
            #pragma unroll
            for (int in = 0; in < 4; in++) mma16816(acc[im][in], ah[im], bl[in]);
        #pragma unroll
        for (int im = 0; im < 4; im++)
            #pragma unroll
            for (int in = 0; in < 4; in++) mma16816(acc[im][in], al[im], bh[in]);
    }
}

__global__ void __launch_bounds__(256) gemm_layer(
    const float* __restrict__ A,
    const __nv_bfloat16* __restrict__ BWh, const __nv_bfloat16* __restrict__ BWl,
    const __nv_bfloat16* __restrict__ BRh, const __nv_bfloat16* __restrict__ BRl,
    const float* __restrict__ avec,
    float* __restrict__ outW, float* __restrict__ outR, int M)
{
    extern __shared__ __nv_bfloat16 sm[];
    float* s_si = (float*)(sm + 2 * BM * L_LDA + 2 * F_SUB);
    float* s_sj = s_si + 128;

    int tid = threadIdx.x, lane = tid & 31, wid = tid >> 5;
    int wm = (wid >> 2) * 64, wn = (wid & 3) * 32;
    int m0 = blockIdx.x * BM;
    uint32_t sbase = smem_u32(sm);

    if (tid < 128) { s_si[tid] = 0.f; s_sj[tid] = 0.f; }

    // stage A once: 128 x 128 fp32 -> hi/lo bf16
    #pragma unroll
    for (int i = 0; i < 16; i++) {
        int idx = i * 256 + tid;
        int r = idx >> 5, c4 = (idx & 31) << 2;
        int gr = m0 + r;
        float4 v = (gr < M) ? *(const float4*)(A + (size_t)gr * FDIM + c4)
                            : make_float4(0.f, 0.f, 0.f, 0.f);
        __nv_bfloat16 h0 = __float2bfloat16(v.x), h1 = __float2bfloat16(v.y);
        __nv_bfloat16 h2 = __float2bfloat16(v.z), h3 = __float2bfloat16(v.w);
        uint2 hp, lp;
        hp.x = (uint32_t)__bfloat16_as_ushort(h0) | ((uint32_t)__bfloat16_as_ushort(h1) << 16);
        hp.y = (uint32_t)__bfloat16_as_ushort(h2) | ((uint32_t)__bfloat16_as_ushort(h3) << 16);
        lp.x = pack2bf(v.x - __bfloat162float(h0), v.y - __bfloat162float(h1));
        lp.y = pack2bf(v.z - __bfloat162float(h2), v.w - __bfloat162float(h3));
        int so = r * L_LDA + c4;
        *(uint2*)&sm[so] = hp;
        *(uint2*)&sm[L_AL + so] = lp;
    }

    int g = lane >> 2, t = lane & 3;

    #pragma unroll
    for (int w = 0; w < 2; w++) {
        const __nv_bfloat16* BH_ = w ? BRh : BWh;
        const __nv_bfloat16* BL_ = w ? BRl : BWl;
        float* outp = w ? outR : outW;

        float acc[4][4][4];
        #pragma unroll
        for (int a = 0; a < 4; a++)
            #pragma unroll
            for (int b = 0; b < 4; b++)
                #pragma unroll
                for (int c = 0; c < 4; c++) acc[a][b][c] = 0.f;

        #pragma unroll
        for (int c = 0; c < 2; c++) {
            __syncthreads();   // previous consumers of B buffer (and A staging on first pass) done
            #pragma unroll
            for (int i = 0; i < 4; i++) {
                int idx = i * 256 + tid;
                int n = idx >> 3, c8 = (idx & 7) << 3;
                size_t go = (size_t)n * FDIM + c * 64 + c8;
                int so = L_B + n * LDSM + c8;
                *(uint4*)&sm[so] = *(const uint4*)&BH_[go];
                *(uint4*)&sm[so + F_SUB] = *(const uint4*)&BL_[go];
            }
            __syncthreads();
            mma_layer(sbase, c, wm, wn, lane, acc);
        }

        if (w == 0) {
            // write Wx + si/sj partials
            #pragma unroll
            for (int im = 0; im < 4; im++) {
                #pragma unroll
                for (int h = 0; h < 2; h++) {
                    int rl = wm + im * 16 + g + h * 8;
                    int row = m0 + rl;
                    float psi = 0.f, psj = 0.f;
                    #pragma unroll
                    for (int in = 0; in < 4; in++) {
                        int col = wn + in * 8 + t * 2;
                        float v0 = acc[im][in][h * 2 + 0];
                        float v1 = acc[im][in][h * 2 + 1];
                        psi += v0 * avec[col] + v1 * avec[col + 1];
                        psj += v0 * avec[FDIM + col] + v1 * avec[FDIM + col + 1];
                        if (row < M)
                            *(float2*)(outp + (size_t)row * FDIM + col) = make_float2(v0, v1);
                    }
                    psi += __shfl_xor_sync(0xFFFFFFFFu, psi, 1);
                    psi += __shfl_xor_sync(0xFFFFFFFFu, psi, 2);
                    psj += __shfl_xor_sync(0xFFFFFFFFu, psj, 1);
                    psj += __shfl_xor_sync(0xFFFFFFFFu, psj, 2);
                    if (t == 0 && row < M) {
                        atomicAdd(&s_si[rl], psi);
                        atomicAdd(&s_sj[rl], psj);
                    }
                }
            }
        } else {
            #pragma unroll
            for (int im = 0; im < 4; im++) {
                #pragma unroll
                for (int in = 0; in < 4; in++) {
                    int col = wn + in * 8 + t * 2;
                    #pragma unroll
                    for (int h = 0; h < 2; h++) {
                        int row = m0 + wm + im * 16 + g + h * 8;
                        if (row < M)
                            *(float2*)(outp + (size_t)row * FDIM + col) =
                                make_float2(acc[im][in][h * 2 + 0], acc[im][in][h * 2 + 1]);
                    }
                }
            }
        }
    }

    __syncthreads();
    if (tid < 128) {
        int gr = m0 + tid;
        if (gr < M) { g_si[gr] = s_si[tid]; g_sj[gr] = s_sj[tid]; }
    }
}

// ---------------- fused softmax + aggregation + residual + ELU ----------------
__global__ void k_softagg(int layer, float* __restrict__ out) {
    int d = (blockIdx.x * blockDim.x + threadIdx.x) >> 5;
    int lane = threadIdx.x & 31;
    if (d >= NN) return;
    int s0 = g_rowptr[d], s1 = g_rowptr[d + 1];
    int deg = s1 - s0;
    const float* srp = g_sr[layer];
    float sid = g_si[d];

    float4 acc = make_float4(0.f, 0.f, 0.f, 0.f);
    float s = 0.f;

    if (deg <= 128) {
        float ev[4]; int sv[4];
        int cnt = (deg + 31) >> 5;
        float m = -1e30f;
        #pragma unroll
        for (int ch = 0; ch < 4; ch++) {
            ev[ch] = -1e30f; sv[ch] = 0;
            if (ch < cnt) {
                int i = s0 + ch * 32 + lane;
                if (i < s1) {
                    int sidx = g_srccsr[i];
                    sv[ch] = sidx;
                    float e = sid + g_sj[sidx] + srp[g_etcsr[i]];
                    ev[ch] = e > 0.f ? e : 0.2f * e;
                }
            }
            m = fmaxf(m, ev[ch]);
        }
        m = wredmax(m);
        #pragma unroll
        for (int ch = 0; ch < 4; ch++) {
            if (ch < cnt) {
                int i = s0 + ch * 32 + lane;
                float ex = (i < s1) ? expf(ev[ch] - m) : 0.f;
                ev[ch] = ex;
                s += ex;
            }
        }
        s = wredsum(s);
        for (int ch = 0; ch < cnt; ch++) {
            int base = s0 + ch * 32;
            int ec = min(32, s1 - base);
            for (int j = 0; j < ec; j++) {
                float al = __shfl_sync(0xFFFFFFFFu, ev[ch], j);
                int sidx = __shfl_sync(0xFFFFFFFFu, sv[ch], j);
                float4 w = *(const float4*)&g_Wx[(size_t)sidx * FDIM + lane * 4];
                acc.x += al * w.x; acc.y += al * w.y;
                acc.z += al * w.z; acc.w += al * w.w;
            }
        }
    } else {
        float m = -1e30f;
        for (int i = s0 + lane; i < s1; i += 32) {
            float e = sid + g_sj[g_srccsr[i]] + srp[g_etcsr[i]];
            e = e > 0.f ? e : 0.2f * e;
            m = fmaxf(m, e);
        }
        m = wredmax(m);
        for (int i = s0 + lane; i < s1; i += 32) {
            float e = sid + g_sj[g_srccsr[i]] + srp[g_etcsr[i]];
            e = e > 0.f ? e : 0.2f * e;
            s += expf(e - m);
        }
        s = wredsum(s);
        for (int i = s0; i < s1; i++) {
            int sidx = g_srccsr[i];
            float e = sid + g_sj[sidx] + srp[g_etcsr[i]];
            e = e > 0.f ? e : 0.2f * e;
            float al = expf(e - m);
            float4 w = *(const float4*)&g_Wx[(size_t)sidx * FDIM + lane * 4];
            acc.x += al * w.x; acc.y += al * w.y;
            acc.z += al * w.z; acc.w += al * w.w;
        }
    }

    float rinv = (deg > 0) ? 1.f / s : 0.f;
    float4 r = *(const float4*)&g_res[(size_t)d * FDIM + lane * 4];
    float4 o;
    o.x = acc.x * rinv + r.x;
    o.y = acc.y * rinv + r.y;
    o.z = acc.z * rinv + r.z;
    o.w = acc.w * rinv + r.w;
    o.x = o.x > 0.f ? o.x : expm1f(o.x);
    o.y = o.y > 0.f ? o.y : expm1f(o.y);
    o.z = o.z > 0.f ? o.z : expm1f(o.z);
    o.w = o.w > 0.f ? o.w : expm1f(o.w);
    *(float4*)&out[(size_t)d * FDIM + lane * 4] = o;
}

// ---------------- output gather + fc3 ----------------
__global__ void k_out(const float* __restrict__ feat, const int* __restrict__ idx,
                      const float* __restrict__ w3, const float* __restrict__ b3,
                      float* __restrict__ out) {
    int i = (blockIdx.x * blockDim.x + threadIdx.x) >> 5;
    int lane = threadIdx.x & 31;
    if (i >= NIDX) return;
    int n = idx[i];
    float4 f = *(const float4*)&feat[(size_t)n * FDIM + lane * 4];
    float fv[4] = {f.x, f.y, f.z, f.w};
    float s0 = 0.f, s1 = 0.f;
    #pragma unroll
    for (int j = 0; j < 4; j++) {
        int k = lane * 4 + j;
        s0 += fv[j] * w3[k * 2 + 0];
        s1 += fv[j] * w3[k * 2 + 1];
    }
    s0 = wredsum(s0);
    s1 = wredsum(s1);
    if (lane == 0) {
        out[i * 2 + 0] = s0 + b3[0];
        out[i * 2 + 1] = s1 + b3[1];
    }
}

// ---------------- host ----------------
extern "C" void kernel_launch(void* const* d_in, const int* in_sizes, int n_in,
                              void* d_out, int out_size) {
    const float* vf    = (const float*)d_in[0];
    const float* tf    = (const float*)d_in[1];
    const float* fc1w  = (const float*)d_in[2];
    const float* fc1b  = (const float*)d_in[3];
    const float* fc2w  = (const float*)d_in[4];
    const float* fc2b  = (const float*)d_in[5];
    const float* reluw = (const float*)d_in[6];
    const float* relub = (const float*)d_in[7];
    const float* l1W   = (const float*)d_in[8];
    const float* l1Wr  = (const float*)d_in[9];
    const float* l1a   = (const float*)d_in[10];
    const float* l1Wres= (const float*)d_in[11];
    const float* l1rel = (const float*)d_in[12];
    const float* l2W   = (const float*)d_in[13];
    const float* l2Wr  = (const float*)d_in[14];
    const float* l2a   = (const float*)d_in[15];
    const float* l2Wres= (const float*)d_in[16];
    const float* l2rel = (const float*)d_in[17];
    const float* fc3w  = (const float*)d_in[18];
    const float* fc3b  = (const float*)d_in[19];
    const int*   eidx  = (const int*)d_in[20];
    const int*   et    = (const int*)d_in[21];
    const int*   idx   = (const int*)d_in[22];
    float*       out   = (float*)d_out;

    const int* src = eidx;
    const int* dst = eidx + NE;

    void *pA, *pB, *pWx, *pRes, *pM2, *pBH, *pBL;
    cudaGetSymbolAddress(&pA,  g_bufA);
    cudaGetSymbolAddress(&pB,  g_bufB);
    cudaGetSymbolAddress(&pWx, g_Wx);
    cudaGetSymbolAddress(&pRes,g_res);
    cudaGetSymbolAddress(&pM2, g_M2);
    cudaGetSymbolAddress(&pBH, g_BH);
    cudaGetSymbolAddress(&pBL, g_BL);
    float* bufA = (float*)pA;
    float* bufB = (float*)pB;
    float* Wx   = (float*)pWx;
    float* res  = (float*)pRes;
    float* M2   = (float*)pM2;
    const __nv_bfloat16* BH = (const __nv_bfloat16*)pBH;
    const __nv_bfloat16* BL = (const __nv_bfloat16*)pBL;

    static int smem_set = 0;
    if (!smem_set) {
        cudaFuncSetAttribute(gemm_front, cudaFuncAttributeMaxDynamicSharedMemorySize, GEMM_FRONT_SMEM);
        cudaFuncSetAttribute(gemm_layer, cudaFuncAttributeMaxDynamicSharedMemorySize, GEMM_LAYER_SMEM);
        smem_set = 1;
    }

    const int NB   = (NN + 255) / 256;
    const int EB   = (NE + 255) / 256;
    const int gW   = (NN * 32 + 255) / 256;
    const int gOut = (NIDX * 32 + 255) / 256;
    const int gPBF = (128 * TDIM + 255) / 256;
    const int gPBL = (128 * FDIM + 255) / 256;

    // --- front-end prep (ordered so ncu -s 5 profiles gemm_front) ---
    k_prepM1<<<1, 256>>>(fc1w, reluw);                       // 0
    k_prepM2<<<TDIM, 128>>>(fc2w, reluw);                    // 1
    k_prepc<<<1, 128>>>(fc1b, fc2b, relub, reluw);           // 2
    k_prepB<<<gPBF, 256>>>(M2, TDIM, SLOT_FRONT);            // 3
    k_prepsr<<<1, 256>>>(l1rel, l1Wr, l1a, 0);               // 4
    gemm_front<<<NTILES, 256, GEMM_FRONT_SMEM>>>(tf, BH + SLOT_FRONT, BL + SLOT_FRONT,
                                                 vf, bufA, NN);   // 5 <- profiled
    // --- remaining prep + CSR build ---
    k_prepsr<<<1, 256>>>(l2rel, l2Wr, l2a, 1);
    k_prepB<<<gPBL, 256>>>(l1W,    FDIM, SLOT_L1W);
    k_prepB<<<gPBL, 256>>>(l1Wres, FDIM, SLOT_L1WRES);
    k_prepB<<<gPBL, 256>>>(l2W,    FDIM, SLOT_L2W);
    k_prepB<<<gPBL, 256>>>(l2Wres, FDIM, SLOT_L2WRES);
    k_zero2<<<NB, 256>>>();
    k_count<<<EB, 256>>>(dst);
    k_scan1<<<NB, 256>>>();
    k_scan2<<<1, 256>>>(NB);
    k_scan3<<<NB, 256>>>();
    k_fill<<<EB, 256>>>(src, dst, et);

    // layer 1: bufA -> bufB
    gemm_layer<<<NTILES, 256, GEMM_LAYER_SMEM>>>(bufA,
        BH + SLOT_L1W, BL + SLOT_L1W, BH + SLOT_L1WRES, BL + SLOT_L1WRES,
        l1a, Wx, res, NN);
    k_softagg<<<gW, 256>>>(0, bufB);

    // layer 2: bufB -> bufA
    gemm_layer<<<NTILES, 256, GEMM_LAYER_SMEM>>>(bufB,
        BH + SLOT_L2W, BL + SLOT_L2W, BH + SLOT_L2WRES, BL + SLOT_L2WRES,
        l2a, Wx, res, NN);
    k_softagg<<<gW, 256>>>(1, bufA);

    // output
    k_out<<<gOut, 256>>>(bufA, idx, fc3w, fc3b, out);
}